// round 15
// baseline (speedup 1.0000x reference)
#include <cuda_runtime.h>
#include <cuda_fp16.h>
#include <math.h>
#include <stddef.h>
#include <stdint.h>

// ---------------- problem constants ----------------
#define BATCH   4
#define SEQ     2048
#define DIM     1024
#define HEADS   16
#define DH      64
#define HID     4096
#define TOK     (BATCH * SEQ)          // 8192
#define EPS     1e-5f
#define ATT_SCALE 0.03125f             // DIM^-0.5 = 1/32
#define LOG2E   1.44269504088896f

// ---------------- scratch (no cudaMalloc allowed) ----------------
__device__ __half g_xn [TOK * DIM];
__device__ __half g_qkv[TOK * 3 * DIM];
__device__ __half g_att[TOK * DIM];
__device__ float  g_x1 [TOK * DIM];
__device__ __half g_h  [TOK * DIM];
__device__ __half g_ff [TOK * HID];
// packed fp16 weights, n-major: [N][K/2] of half2 k-pairs
__device__ unsigned g_wqkv[3 * DIM * (DIM / 2)];
__device__ unsigned g_wout[DIM * (DIM / 2)];
__device__ unsigned g_w1  [HID * (DIM / 2)];
__device__ unsigned g_w2  [DIM * (HID / 2)];

// ---------------- helpers ----------------
__device__ __forceinline__ void cp16(unsigned dst, const void* src) {
    asm volatile("cp.async.cg.shared.global [%0], [%1], 16;" :: "r"(dst), "l"(src));
}
__device__ __forceinline__ void cp_commit() {
    asm volatile("cp.async.commit_group;" ::: "memory");
}
__device__ __forceinline__ void cp_wait0() {
    asm volatile("cp.async.wait_group 0;" ::: "memory");
}

__device__ __forceinline__ void mma_fp16(
    float* c, const unsigned* a, unsigned b0, unsigned b1)
{
    asm volatile(
        "mma.sync.aligned.m16n8k16.row.col.f32.f16.f16.f32 "
        "{%0,%1,%2,%3}, {%4,%5,%6,%7}, {%8,%9}, {%0,%1,%2,%3};"
        : "+f"(c[0]), "+f"(c[1]), "+f"(c[2]), "+f"(c[3])
        : "r"(a[0]), "r"(a[1]), "r"(a[2]), "r"(a[3]), "r"(b0), "r"(b1));
}

__device__ __forceinline__ void ldsm_x4(
    unsigned& d0, unsigned& d1, unsigned& d2, unsigned& d3, unsigned addr)
{
    asm volatile("ldmatrix.sync.aligned.m8n8.x4.shared.b16 {%0,%1,%2,%3}, [%4];"
                 : "=r"(d0), "=r"(d1), "=r"(d2), "=r"(d3) : "r"(addr));
}
__device__ __forceinline__ void ldsm_x4_t(
    unsigned& d0, unsigned& d1, unsigned& d2, unsigned& d3, unsigned addr)
{
    asm volatile("ldmatrix.sync.aligned.m8n8.x4.trans.shared.b16 {%0,%1,%2,%3}, [%4];"
                 : "=r"(d0), "=r"(d1), "=r"(d2), "=r"(d3) : "r"(addr));
}

__device__ __forceinline__ unsigned ex2_f16x2(unsigned in) {
    unsigned out;
    asm("ex2.approx.f16x2 %0, %1;" : "=r"(out) : "r"(in));
    return out;
}

// =====================================================================
// transpose-pack: out[n][k2] = half2(w[2k2][n], w[2k2+1][n])
// =====================================================================
__global__ void __launch_bounds__(256) packT_w_kernel(
    const float* __restrict__ w, unsigned* __restrict__ out, int K, int N)
{
    __shared__ unsigned tile[32][33];
    int K2 = K >> 1;
    int bn = blockIdx.x * 32;
    int bk2 = blockIdx.y * 32;
    int tx = threadIdx.x & 31;
    int ty = threadIdx.x >> 5;
#pragma unroll
    for (int i = 0; i < 4; i++) {
        int k2 = bk2 + ty + i * 8;
        float lo = w[(size_t)(2 * k2) * N + bn + tx];
        float hi = w[(size_t)(2 * k2 + 1) * N + bn + tx];
        __half2 h = __floats2half2_rn(lo, hi);
        tile[ty + i * 8][tx] = *(unsigned*)&h;
    }
    __syncthreads();
#pragma unroll
    for (int i = 0; i < 4; i++) {
        int n = bn + ty + i * 8;
        out[(size_t)n * K2 + bk2 + tx] = tile[tx][ty + i * 8];
    }
}

// =====================================================================
// LayerNorm (torch semantics), warp-per-row, fp16 output.
// =====================================================================
__global__ void __launch_bounds__(256) ln_kernel(
    const float* __restrict__ x, const float* __restrict__ gamma,
    const float* __restrict__ beta, __half* __restrict__ y)
{
    int row = blockIdx.x * 8 + (threadIdx.x >> 5);
    int lane = threadIdx.x & 31;
    const float* xr = x + (size_t)row * DIM;

    float4 v[8];
    float s = 0.f;
#pragma unroll
    for (int i = 0; i < 8; i++) {
        v[i] = *(const float4*)(xr + (i * 32 + lane) * 4);
        s += (v[i].x + v[i].y) + (v[i].z + v[i].w);
    }
#pragma unroll
    for (int o = 16; o > 0; o >>= 1) s += __shfl_xor_sync(0xffffffffu, s, o);
    float mean = s * (1.0f / DIM);

    float ss = 0.f;
#pragma unroll
    for (int i = 0; i < 8; i++) {
        float dx = v[i].x - mean, dy = v[i].y - mean;
        float dz = v[i].z - mean, dw = v[i].w - mean;
        ss += (dx * dx + dy * dy) + (dz * dz + dw * dw);
    }
#pragma unroll
    for (int o = 16; o > 0; o >>= 1) ss += __shfl_xor_sync(0xffffffffu, ss, o);

    float inv = 1.0f / (sqrtf(ss * (1.0f / (DIM - 1))) + EPS);

    __half* yr = y + (size_t)row * DIM;
#pragma unroll
    for (int i = 0; i < 8; i++) {
        int c = (i * 32 + lane) * 4;
        float4 gv = *(const float4*)(gamma + c);
        float4 bv = *(const float4*)(beta + c);
        __half2 h01 = __floats2half2_rn(gv.x * (v[i].x - mean) * inv + bv.x,
                                        gv.y * (v[i].y - mean) * inv + bv.y);
        __half2 h23 = __floats2half2_rn(gv.z * (v[i].z - mean) * inv + bv.z,
                                        gv.w * (v[i].w - mean) * inv + bv.w);
        __half2* yp = (__half2*)(yr + c);
        yp[0] = h01;
        yp[1] = h23;
    }
}

// =====================================================================
// fp16 tensor-core GEMM. BM=BN=128, BK=64 halves, 128 threads = 4 warps.
// 2-stage cp.async pipeline, 3 CTAs/SM for wave-quantization + latency.
// A/B frags via ldmatrix; 1 sync per K-tile.
// =====================================================================
#define AH_STRIDE 72
#define A_BUF_BYTES (128 * AH_STRIDE * 2)     // 18432
#define BT_STRIDE 36                          // words
#define B_BUF_BYTES (128 * BT_STRIDE * 4)     // 18432
#define STAGE_BYTES (A_BUF_BYTES + B_BUF_BYTES)             // 36864
#define GEMM_SMEM_BYTES (2 * STAGE_BYTES)                   // 73728

template <typename OutT, bool BIAS, bool RELU, bool RES>
__global__ void __launch_bounds__(128, 3) gemm_fp16_kernel(
    const __half* __restrict__ A, const unsigned* __restrict__ Bp,
    const float* __restrict__ bias, const float* __restrict__ res,
    OutT* __restrict__ C, int M, int N, int K)
{
    extern __shared__ char smraw[];
    unsigned sbase = (unsigned)__cvta_generic_to_shared(smraw);

    int tid = threadIdx.x;
    int warp = tid >> 5;
    int lane = tid & 31;
    int bm = blockIdx.y * 128;
    int bn = blockIdx.x * 128;
    int wm = (warp & 1) * 64;
    int wn = (warp >> 1) * 64;
    int gg = lane >> 2;
    int cc = lane & 3;
    int K2 = K >> 1;

    float acc[4][8][4];
#pragma unroll
    for (int f = 0; f < 4; f++)
#pragma unroll
        for (int nf = 0; nf < 8; nf++)
#pragma unroll
            for (int q = 0; q < 4; q++) acc[f][nf][q] = 0.f;

    auto load_tiles = [&](int t, int s) {
        int k0 = t * 64;
        unsigned abase = sbase + s * STAGE_BYTES;
        unsigned bbase = abase + A_BUF_BYTES;
#pragma unroll
        for (int j = 0; j < 8; j++) {
            int idx = tid + j * 128;
            int r = idx >> 3, c = idx & 7;
            cp16(abase + r * (AH_STRIDE * 2) + c * 16,
                 A + (size_t)(bm + r) * K + k0 + c * 8);
        }
#pragma unroll
        for (int j = 0; j < 8; j++) {
            int idx = tid + j * 128;
            int r = idx >> 3, c = idx & 7;
            cp16(bbase + r * (BT_STRIDE * 4) + c * 16,
                 Bp + (size_t)(bn + r) * K2 + (k0 >> 1) + c * 4);
        }
        cp_commit();
    };

    int nT = K >> 6;
    load_tiles(0, 0);

    int lrow = lane & 15;
    int lkof = (lane & 16) ? 8 : 0;
    int bmm = lane >> 3;
    int b_nf_half = bmm >> 1;
    int b_koff = (bmm & 1) * 4;
    int b_r8 = lane & 7;

    for (int t = 0; t < nT; t++) {
        cp_wait0();
        __syncthreads();
        if (t + 1 < nT) load_tiles(t + 1, (t + 1) & 1);

        unsigned abase = sbase + (t & 1) * STAGE_BYTES;
        unsigned bbase = abase + A_BUF_BYTES;

#pragma unroll
        for (int ks = 0; ks < 4; ks++) {
            int kb = ks * 16;
            unsigned a[4][4], b[8][2];
#pragma unroll
            for (int f = 0; f < 4; f++) {
                unsigned addr = abase +
                    ((unsigned)(wm + f * 16 + lrow) * AH_STRIDE + (unsigned)(kb + lkof)) * 2;
                ldsm_x4(a[f][0], a[f][1], a[f][2], a[f][3], addr);
            }
#pragma unroll
            for (int p = 0; p < 4; p++) {
                unsigned addr = bbase +
                    ((unsigned)(wn + (2 * p + b_nf_half) * 8 + b_r8) * BT_STRIDE
                     + (unsigned)(ks * 8 + b_koff)) * 4;
                ldsm_x4(b[2 * p][0], b[2 * p][1], b[2 * p + 1][0], b[2 * p + 1][1], addr);
            }
#pragma unroll
            for (int f = 0; f < 4; f++)
#pragma unroll
                for (int nf = 0; nf < 8; nf++)
                    mma_fp16(acc[f][nf], a[f], b[nf][0], b[nf][1]);
        }
    }

#pragma unroll
    for (int f = 0; f < 4; f++) {
#pragma unroll
        for (int nf = 0; nf < 8; nf++) {
            int col = bn + wn + nf * 8 + 2 * cc;
#pragma unroll
            for (int half_i = 0; half_i < 2; half_i++) {
                int row = bm + wm + f * 16 + gg + half_i * 8;
                float v0 = acc[f][nf][half_i * 2 + 0];
                float v1 = acc[f][nf][half_i * 2 + 1];
                if (BIAS) { v0 += bias[col]; v1 += bias[col + 1]; }
                if (RES) {
                    const float* rp = res + (size_t)row * N + col;
                    v0 += rp[0]; v1 += rp[1];
                }
                if (RELU) { v0 = fmaxf(v0, 0.f); v1 = fmaxf(v1, 0.f); }
                if (sizeof(OutT) == 2) {
                    __half2 hv = __floats2half2_rn(v0, v1);
                    *(__half2*)((__half*)C + (size_t)row * N + col) = hv;
                } else {
                    float2 w; w.x = v0; w.y = v1;
                    *(float2*)((float*)C + (size_t)row * N + col) = w;
                }
            }
        }
    }
}

// =====================================================================
// fp16 flash attention (R10 structure).
// =====================================================================
#define KSW_BYTES 8192
#define P2_STRIDE 36
#define P2_BYTES  (128 * P2_STRIDE * 4)
#define ATTF_SMEM (4 * KSW_BYTES + P2_BYTES)  // 51200

__global__ void __launch_bounds__(256) attn_fp16_kernel(
    const __half* __restrict__ qkv, __half* __restrict__ out)
{
    extern __shared__ char sm[];
    unsigned sbase = (unsigned)__cvta_generic_to_shared(sm);
    unsigned* p2sm = (unsigned*)(sm + 4 * KSW_BYTES);
    unsigned p2base = sbase + 4 * KSW_BYTES;

    int tid = threadIdx.x;
    int warp = tid >> 5;
    int lane = tid & 31;
    int gg = lane >> 2;
    int cc = lane & 3;
    int wm = warp * 16;

    int bh = blockIdx.y;
    int b = bh >> 4;
    int h = bh & 15;
    size_t tokbase = (size_t)b * SEQ + blockIdx.x * 128;
    const __half* qb = qkv + tokbase * (3 * DIM) + h * DH;

    auto load_kv = [&](int kt, int s) {
        const __half* kp = qkv + ((size_t)b * SEQ + kt) * (3 * DIM) + DIM + h * DH;
        const __half* vp = kp + DIM;
        unsigned kdst = sbase + s * KSW_BYTES;
        unsigned vdst = sbase + (2 + s) * KSW_BYTES;
#pragma unroll
        for (int j = 0; j < 2; j++) {
            int idx = tid + j * 256;
            int r = idx >> 3, c = idx & 7;
            unsigned off = (unsigned)(r * 128 + c * 16);
            unsigned sw = off ^ ((unsigned)(r & 7) << 4);
            cp16(kdst + sw, kp + (size_t)r * (3 * DIM) + c * 8);
            cp16(vdst + sw, vp + (size_t)r * (3 * DIM) + c * 8);
        }
        cp_commit();
    };

    load_kv(0, 0);

    unsigned qf[4][4];
    {
        const float SC = ATT_SCALE * LOG2E;
        const __half* r0 = qb + (size_t)(wm + gg) * (3 * DIM);
        const __half* r1 = qb + (size_t)(wm + gg + 8) * (3 * DIM);
#pragma unroll
        for (int kf = 0; kf < 4; kf++) {
            int c0 = kf * 16 + 2 * cc;
#pragma unroll
            for (int q = 0; q < 4; q++) {
                const __half* rp = (q & 1) ? r1 : r0;
                int cofs = c0 + ((q >> 1) ? 8 : 0);
                float2 f = __half22float2(*(const __half2*)(rp + cofs));
                __half2 v = __floats2half2_rn(f.x * SC, f.y * SC);
                qf[kf][q] = *(unsigned*)&v;
            }
        }
    }

    float of[8][4];
#pragma unroll
    for (int nf = 0; nf < 8; nf++)
#pragma unroll
        for (int q = 0; q < 4; q++) of[nf][q] = 0.f;
    float m0 = -1e30f, m1 = -1e30f, l0 = 0.f, l1 = 0.f;

    int l15 = lane & 15;

    for (int t = 0; t < SEQ / 64; t++) {
        cp_wait0();
        __syncthreads();
        if (t + 1 < SEQ / 64) load_kv((t + 1) * 64, (t + 1) & 1);

        unsigned kb_s = sbase + (t & 1) * KSW_BYTES;
        unsigned vb_s = sbase + (2 + (t & 1)) * KSW_BYTES;

        float s[8][4];
#pragma unroll
        for (int nf = 0; nf < 8; nf++)
#pragma unroll
            for (int q = 0; q < 4; q++) s[nf][q] = 0.f;

#pragma unroll
        for (int kf = 0; kf < 4; kf++) {
#pragma unroll
            for (int nfp = 0; nfp < 4; nfp++) {
                unsigned row = (unsigned)(nfp * 16 + (lane & 7) + ((lane & 16) ? 8 : 0));
                unsigned off = row * 128 + (unsigned)(kf * 32 + ((lane & 8) ? 16 : 0));
                unsigned addr = kb_s + (off ^ ((row & 7) << 4));
                unsigned b0, b1, b2, b3;
                ldsm_x4(b0, b1, b2, b3, addr);
                mma_fp16(s[2 * nfp], qf[kf], b0, b1);
                mma_fp16(s[2 * nfp + 1], qf[kf], b2, b3);
            }
        }

        float rmax0 = -1e30f, rmax1 = -1e30f;
#pragma unroll
        for (int nf = 0; nf < 8; nf++) {
            rmax0 = fmaxf(rmax0, fmaxf(s[nf][0], s[nf][1]));
            rmax1 = fmaxf(rmax1, fmaxf(s[nf][2], s[nf][3]));
        }
        rmax0 = fmaxf(rmax0, __shfl_xor_sync(0xffffffffu, rmax0, 1));
        rmax0 = fmaxf(rmax0, __shfl_xor_sync(0xffffffffu, rmax0, 2));
        rmax1 = fmaxf(rmax1, __shfl_xor_sync(0xffffffffu, rmax1, 1));
        rmax1 = fmaxf(rmax1, __shfl_xor_sync(0xffffffffu, rmax1, 2));

        float mn0 = fmaxf(m0, rmax0);
        float mn1 = fmaxf(m1, rmax1);
        float f0 = exp2f(m0 - mn0);
        float f1 = exp2f(m1 - mn1);
        m0 = mn0; m1 = mn1;

        float rs0 = 0.f, rs1 = 0.f;
#pragma unroll
        for (int nf = 0; nf < 8; nf++) {
            __half2 hd0 = __floats2half2_rn(s[nf][0] - mn0, s[nf][1] - mn0);
            __half2 hd1 = __floats2half2_rn(s[nf][2] - mn1, s[nf][3] - mn1);
            unsigned hp0 = ex2_f16x2(*(unsigned*)&hd0);
            unsigned hp1 = ex2_f16x2(*(unsigned*)&hd1);
            float2 pf0 = __half22float2(*(__half2*)&hp0);
            float2 pf1 = __half22float2(*(__half2*)&hp1);
            rs0 += pf0.x + pf0.y;
            rs1 += pf1.x + pf1.y;
            p2sm[(wm + gg) * P2_STRIDE + nf * 4 + cc] = hp0;
            p2sm[(wm + gg + 8) * P2_STRIDE + nf * 4 + cc] = hp1;
        }
        rs0 += __shfl_xor_sync(0xffffffffu, rs0, 1);
        rs0 += __shfl_xor_sync(0xffffffffu, rs0, 2);
        rs1 += __shfl_xor_sync(0xffffffffu, rs1, 1);
        rs1 += __shfl_xor_sync(0xffffffffu, rs1, 2);
        l0 = l0 * f0 + rs0;
        l1 = l1 * f1 + rs1;

#pragma unroll
        for (int nf = 0; nf < 8; nf++) {
            of[nf][0] *= f0; of[nf][1] *= f0;
            of[nf][2] *= f1; of[nf][3] *= f1;
        }
        __syncwarp();

#pragma unroll
        for (int kf = 0; kf < 4; kf++) {
            unsigned a[4];
            unsigned pa = p2base + (unsigned)(wm + l15) * (P2_STRIDE * 4)
                        + (unsigned)(kf * 32 + ((lane & 16) ? 16 : 0));
            ldsm_x4(a[0], a[1], a[2], a[3], pa);
#pragma unroll
            for (int nfp = 0; nfp < 4; nfp++) {
                unsigned row = (unsigned)(kf * 16 + l15);
                unsigned off = row * 128 + (unsigned)(nfp * 32 + ((lane & 16) ? 16 : 0));
                unsigned addr = vb_s + (off ^ ((row & 7) << 4));
                unsigned b0, b1, b2, b3;
                ldsm_x4_t(b0, b1, b2, b3, addr);
                mma_fp16(of[2 * nfp], a, b0, b1);
                mma_fp16(of[2 * nfp + 1], a, b2, b3);
            }
        }
    }

    float inv0 = 1.0f / l0;
    float inv1 = 1.0f / l1;
    __half* op = out + tokbase * DIM + h * DH;
#pragma unroll
    for (int nf = 0; nf < 8; nf++) {
        int c0 = nf * 8 + 2 * cc;
        __half2 w0 = __floats2half2_rn(of[nf][0] * inv0, of[nf][1] * inv0);
        __half2 w1 = __floats2half2_rn(of[nf][2] * inv1, of[nf][3] * inv1);
        *(__half2*)(op + (size_t)(wm + gg) * DIM + c0)     = w0;
        *(__half2*)(op + (size_t)(wm + gg + 8) * DIM + c0) = w1;
    }
}

// =====================================================================
// launch — packs on side stream (overlapped), 2-stage/3-CTA GEMMs.
// =====================================================================
extern "C" void kernel_launch(void* const* d_in, const int* in_sizes, int n_in,
                              void* d_out, int out_size)
{
    const float* x      = (const float*)d_in[0];
    const float* w_qkv  = (const float*)d_in[1];
    const float* w_out  = (const float*)d_in[2];
    const float* b_out  = (const float*)d_in[3];
    const float* w1     = (const float*)d_in[4];
    const float* b1     = (const float*)d_in[5];
    const float* w2     = (const float*)d_in[6];
    const float* b2     = (const float*)d_in[7];
    const float* gamma1 = (const float*)d_in[8];
    const float* beta1  = (const float*)d_in[9];
    const float* gamma2 = (const float*)d_in[10];
    const float* beta2  = (const float*)d_in[11];
    float* out = (float*)d_out;

    __half *xn, *qkv, *att, *h, *ff;
    float *x1;
    unsigned *wqkv, *wout, *w1p, *w2p;
    cudaGetSymbolAddress((void**)&xn,   g_xn);
    cudaGetSymbolAddress((void**)&qkv,  g_qkv);
    cudaGetSymbolAddress((void**)&att,  g_att);
    cudaGetSymbolAddress((void**)&x1,   g_x1);
    cudaGetSymbolAddress((void**)&h,    g_h);
    cudaGetSymbolAddress((void**)&ff,   g_ff);
    cudaGetSymbolAddress((void**)&wqkv, g_wqkv);
    cudaGetSymbolAddress((void**)&wout, g_wout);
    cudaGetSymbolAddress((void**)&w1p,  g_w1);
    cudaGetSymbolAddress((void**)&w2p,  g_w2);

    static bool init_done = false;
    static cudaStream_t sB;
    static cudaEvent_t evFork, evQkv, evRest;
    if (!init_done) {
        cudaFuncSetAttribute(gemm_fp16_kernel<__half, false, false, false>,
                             cudaFuncAttributeMaxDynamicSharedMemorySize, GEMM_SMEM_BYTES);
        cudaFuncSetAttribute(gemm_fp16_kernel<float, true, false, true>,
                             cudaFuncAttributeMaxDynamicSharedMemorySize, GEMM_SMEM_BYTES);
        cudaFuncSetAttribute(gemm_fp16_kernel<__half, true, true, false>,
                             cudaFuncAttributeMaxDynamicSharedMemorySize, GEMM_SMEM_BYTES);
        cudaFuncSetAttribute(attn_fp16_kernel,
                             cudaFuncAttributeMaxDynamicSharedMemorySize, ATTF_SMEM);
        cudaStreamCreateWithFlags(&sB, cudaStreamNonBlocking);
        cudaEventCreateWithFlags(&evFork, cudaEventDisableTiming);
        cudaEventCreateWithFlags(&evQkv,  cudaEventDisableTiming);
        cudaEventCreateWithFlags(&evRest, cudaEventDisableTiming);
        init_done = true;
    }

    // ---- fork side stream ----
    cudaEventRecord(evFork, 0);
    cudaStreamWaitEvent(sB, evFork, 0);

    packT_w_kernel<<<dim3(3 * DIM / 32, DIM / 64), 256, 0, sB>>>(w_qkv, wqkv, DIM, 3 * DIM);
    cudaEventRecord(evQkv, sB);
    packT_w_kernel<<<dim3(DIM / 32, DIM / 64), 256, 0, sB>>>(w_out, wout, DIM, DIM);
    packT_w_kernel<<<dim3(HID / 32, DIM / 64), 256, 0, sB>>>(w1, w1p, DIM, HID);
    packT_w_kernel<<<dim3(DIM / 32, HID / 64), 256, 0, sB>>>(w2, w2p, HID, DIM);
    cudaEventRecord(evRest, sB);

    // 1) xn = fp16(LN1(x))
    ln_kernel<<<TOK / 8, 256>>>(x, gamma1, beta1, xn);

    cudaStreamWaitEvent(0, evQkv, 0);

    // 2) qkv = fp16(xn @ w_qkv)
    gemm_fp16_kernel<__half, false, false, false>
        <<<dim3(3 * DIM / 128, TOK / 128), 128, GEMM_SMEM_BYTES>>>(
        xn, wqkv, nullptr, nullptr, qkv, TOK, 3 * DIM, DIM);

    // 3) att = fp16(attention(qkv))
    attn_fp16_kernel<<<dim3(SEQ / 128, BATCH * HEADS), 256, ATTF_SMEM>>>(qkv, att);

    cudaStreamWaitEvent(0, evRest, 0);

    // 4) x1 = x + att @ w_out + b_out    (fp32)
    gemm_fp16_kernel<float, true, false, true>
        <<<dim3(DIM / 128, TOK / 128), 128, GEMM_SMEM_BYTES>>>(
        att, wout, b_out, x, x1, TOK, DIM, DIM);

    // 5) h = fp16(LN2(x1))
    ln_kernel<<<TOK / 8, 256>>>(x1, gamma2, beta2, h);

    // 6) ff = fp16(relu(h @ w1 + b1))
    gemm_fp16_kernel<__half, true, true, false>
        <<<dim3(HID / 128, TOK / 128), 128, GEMM_SMEM_BYTES>>>(
        h, w1p, b1, nullptr, ff, TOK, HID, DIM);

    // 7) out = x1 + ff @ w2 + b2   (fp32)
    gemm_fp16_kernel<float, true, false, true>
        <<<dim3(DIM / 128, TOK / 128), 128, GEMM_SMEM_BYTES>>>(
        ff, w2p, b2, x1, out, TOK, DIM, HID);
}

// round 16
// speedup vs baseline: 1.5243x; 1.5243x over previous
#include <cuda_runtime.h>
#include <cuda_fp16.h>
#include <math.h>
#include <stddef.h>
#include <stdint.h>

// ---------------- problem constants ----------------
#define BATCH   4
#define SEQ     2048
#define DIM     1024
#define HEADS   16
#define DH      64
#define HID     4096
#define TOK     (BATCH * SEQ)          // 8192
#define EPS     1e-5f
#define ATT_SCALE 0.03125f             // DIM^-0.5 = 1/32
#define LOG2E   1.44269504088896f

// ---------------- scratch (no cudaMalloc allowed) ----------------
__device__ __half g_xn [TOK * DIM];
__device__ __half g_qkv[TOK * 3 * DIM];
__device__ __half g_att[TOK * DIM];
__device__ float  g_x1 [TOK * DIM];
__device__ __half g_h  [TOK * DIM];
__device__ __half g_ff [TOK * HID];
// packed fp16 weights, n-major: [N][K/2] of half2 k-pairs
__device__ unsigned g_wqkv[3 * DIM * (DIM / 2)];
__device__ unsigned g_wout[DIM * (DIM / 2)];
__device__ unsigned g_w1  [HID * (DIM / 2)];
__device__ unsigned g_w2  [DIM * (HID / 2)];

// ---------------- helpers ----------------
__device__ __forceinline__ void cp16(unsigned dst, const void* src) {
    asm volatile("cp.async.cg.shared.global [%0], [%1], 16;" :: "r"(dst), "l"(src));
}
__device__ __forceinline__ void cp_commit() {
    asm volatile("cp.async.commit_group;" ::: "memory");
}
__device__ __forceinline__ void cp_wait0() {
    asm volatile("cp.async.wait_group 0;" ::: "memory");
}

__device__ __forceinline__ void mma_fp16(
    float* c, const unsigned* a, unsigned b0, unsigned b1)
{
    asm volatile(
        "mma.sync.aligned.m16n8k16.row.col.f32.f16.f16.f32 "
        "{%0,%1,%2,%3}, {%4,%5,%6,%7}, {%8,%9}, {%0,%1,%2,%3};"
        : "+f"(c[0]), "+f"(c[1]), "+f"(c[2]), "+f"(c[3])
        : "r"(a[0]), "r"(a[1]), "r"(a[2]), "r"(a[3]), "r"(b0), "r"(b1));
}

__device__ __forceinline__ void ldsm_x4(
    unsigned& d0, unsigned& d1, unsigned& d2, unsigned& d3, unsigned addr)
{
    asm volatile("ldmatrix.sync.aligned.m8n8.x4.shared.b16 {%0,%1,%2,%3}, [%4];"
                 : "=r"(d0), "=r"(d1), "=r"(d2), "=r"(d3) : "r"(addr));
}
__device__ __forceinline__ void ldsm_x4_t(
    unsigned& d0, unsigned& d1, unsigned& d2, unsigned& d3, unsigned addr)
{
    asm volatile("ldmatrix.sync.aligned.m8n8.x4.trans.shared.b16 {%0,%1,%2,%3}, [%4];"
                 : "=r"(d0), "=r"(d1), "=r"(d2), "=r"(d3) : "r"(addr));
}

__device__ __forceinline__ unsigned ex2_f16x2(unsigned in) {
    unsigned out;
    asm("ex2.approx.f16x2 %0, %1;" : "=r"(out) : "r"(in));
    return out;
}

// =====================================================================
// transpose-pack: out[n][k2] = half2(w[2k2][n], w[2k2+1][n])
// =====================================================================
__global__ void __launch_bounds__(256) packT_w_kernel(
    const float* __restrict__ w, unsigned* __restrict__ out, int K, int N)
{
    __shared__ unsigned tile[32][33];
    int K2 = K >> 1;
    int bn = blockIdx.x * 32;
    int bk2 = blockIdx.y * 32;
    int tx = threadIdx.x & 31;
    int ty = threadIdx.x >> 5;
#pragma unroll
    for (int i = 0; i < 4; i++) {
        int k2 = bk2 + ty + i * 8;
        float lo = w[(size_t)(2 * k2) * N + bn + tx];
        float hi = w[(size_t)(2 * k2 + 1) * N + bn + tx];
        __half2 h = __floats2half2_rn(lo, hi);
        tile[ty + i * 8][tx] = *(unsigned*)&h;
    }
    __syncthreads();
#pragma unroll
    for (int i = 0; i < 4; i++) {
        int n = bn + ty + i * 8;
        out[(size_t)n * K2 + bk2 + tx] = tile[tx][ty + i * 8];
    }
}

// =====================================================================
// LayerNorm (torch semantics), warp-per-row, fp16 output.
// =====================================================================
__global__ void __launch_bounds__(256) ln_kernel(
    const float* __restrict__ x, const float* __restrict__ gamma,
    const float* __restrict__ beta, __half* __restrict__ y)
{
    int row = blockIdx.x * 8 + (threadIdx.x >> 5);
    int lane = threadIdx.x & 31;
    const float* xr = x + (size_t)row * DIM;

    float4 v[8];
    float s = 0.f;
#pragma unroll
    for (int i = 0; i < 8; i++) {
        v[i] = *(const float4*)(xr + (i * 32 + lane) * 4);
        s += (v[i].x + v[i].y) + (v[i].z + v[i].w);
    }
#pragma unroll
    for (int o = 16; o > 0; o >>= 1) s += __shfl_xor_sync(0xffffffffu, s, o);
    float mean = s * (1.0f / DIM);

    float ss = 0.f;
#pragma unroll
    for (int i = 0; i < 8; i++) {
        float dx = v[i].x - mean, dy = v[i].y - mean;
        float dz = v[i].z - mean, dw = v[i].w - mean;
        ss += (dx * dx + dy * dy) + (dz * dz + dw * dw);
    }
#pragma unroll
    for (int o = 16; o > 0; o >>= 1) ss += __shfl_xor_sync(0xffffffffu, ss, o);

    float inv = 1.0f / (sqrtf(ss * (1.0f / (DIM - 1))) + EPS);

    __half* yr = y + (size_t)row * DIM;
#pragma unroll
    for (int i = 0; i < 8; i++) {
        int c = (i * 32 + lane) * 4;
        float4 gv = *(const float4*)(gamma + c);
        float4 bv = *(const float4*)(beta + c);
        __half2 h01 = __floats2half2_rn(gv.x * (v[i].x - mean) * inv + bv.x,
                                        gv.y * (v[i].y - mean) * inv + bv.y);
        __half2 h23 = __floats2half2_rn(gv.z * (v[i].z - mean) * inv + bv.z,
                                        gv.w * (v[i].w - mean) * inv + bv.w);
        __half2* yp = (__half2*)(yr + c);
        yp[0] = h01;
        yp[1] = h23;
    }
}

// =====================================================================
// fp16 tensor-core GEMM. BM=BN=128, BK=64 halves, 128 threads = 4 warps.
// 2-stage cp.async pipeline, 2 CTAs/SM (register-limited; 3 spills).
// A/B frags via ldmatrix; 1 sync per K-tile.
// =====================================================================
#define AH_STRIDE 72
#define A_BUF_BYTES (128 * AH_STRIDE * 2)     // 18432
#define BT_STRIDE 36                          // words
#define B_BUF_BYTES (128 * BT_STRIDE * 4)     // 18432
#define STAGE_BYTES (A_BUF_BYTES + B_BUF_BYTES)             // 36864
#define GEMM_SMEM_BYTES (2 * STAGE_BYTES)                   // 73728

template <typename OutT, bool BIAS, bool RELU, bool RES>
__global__ void __launch_bounds__(128, 2) gemm_fp16_kernel(
    const __half* __restrict__ A, const unsigned* __restrict__ Bp,
    const float* __restrict__ bias, const float* __restrict__ res,
    OutT* __restrict__ C, int M, int N, int K)
{
    extern __shared__ char smraw[];
    unsigned sbase = (unsigned)__cvta_generic_to_shared(smraw);

    int tid = threadIdx.x;
    int warp = tid >> 5;
    int lane = tid & 31;
    int bm = blockIdx.y * 128;
    int bn = blockIdx.x * 128;
    int wm = (warp & 1) * 64;
    int wn = (warp >> 1) * 64;
    int gg = lane >> 2;
    int cc = lane & 3;
    int K2 = K >> 1;

    float acc[4][8][4];
#pragma unroll
    for (int f = 0; f < 4; f++)
#pragma unroll
        for (int nf = 0; nf < 8; nf++)
#pragma unroll
            for (int q = 0; q < 4; q++) acc[f][nf][q] = 0.f;

    auto load_tiles = [&](int t, int s) {
        int k0 = t * 64;
        unsigned abase = sbase + s * STAGE_BYTES;
        unsigned bbase = abase + A_BUF_BYTES;
#pragma unroll
        for (int j = 0; j < 8; j++) {
            int idx = tid + j * 128;
            int r = idx >> 3, c = idx & 7;
            cp16(abase + r * (AH_STRIDE * 2) + c * 16,
                 A + (size_t)(bm + r) * K + k0 + c * 8);
        }
#pragma unroll
        for (int j = 0; j < 8; j++) {
            int idx = tid + j * 128;
            int r = idx >> 3, c = idx & 7;
            cp16(bbase + r * (BT_STRIDE * 4) + c * 16,
                 Bp + (size_t)(bn + r) * K2 + (k0 >> 1) + c * 4);
        }
        cp_commit();
    };

    int nT = K >> 6;
    load_tiles(0, 0);

    int lrow = lane & 15;
    int lkof = (lane & 16) ? 8 : 0;
    int bmm = lane >> 3;
    int b_nf_half = bmm >> 1;
    int b_koff = (bmm & 1) * 4;
    int b_r8 = lane & 7;

    for (int t = 0; t < nT; t++) {
        cp_wait0();
        __syncthreads();
        if (t + 1 < nT) load_tiles(t + 1, (t + 1) & 1);

        unsigned abase = sbase + (t & 1) * STAGE_BYTES;
        unsigned bbase = abase + A_BUF_BYTES;

#pragma unroll
        for (int ks = 0; ks < 4; ks++) {
            int kb = ks * 16;
            unsigned a[4][4], b[8][2];
#pragma unroll
            for (int f = 0; f < 4; f++) {
                unsigned addr = abase +
                    ((unsigned)(wm + f * 16 + lrow) * AH_STRIDE + (unsigned)(kb + lkof)) * 2;
                ldsm_x4(a[f][0], a[f][1], a[f][2], a[f][3], addr);
            }
#pragma unroll
            for (int p = 0; p < 4; p++) {
                unsigned addr = bbase +
                    ((unsigned)(wn + (2 * p + b_nf_half) * 8 + b_r8) * BT_STRIDE
                     + (unsigned)(ks * 8 + b_koff)) * 4;
                ldsm_x4(b[2 * p][0], b[2 * p][1], b[2 * p + 1][0], b[2 * p + 1][1], addr);
            }
#pragma unroll
            for (int f = 0; f < 4; f++)
#pragma unroll
                for (int nf = 0; nf < 8; nf++)
                    mma_fp16(acc[f][nf], a[f], b[nf][0], b[nf][1]);
        }
    }

#pragma unroll
    for (int f = 0; f < 4; f++) {
#pragma unroll
        for (int nf = 0; nf < 8; nf++) {
            int col = bn + wn + nf * 8 + 2 * cc;
#pragma unroll
            for (int half_i = 0; half_i < 2; half_i++) {
                int row = bm + wm + f * 16 + gg + half_i * 8;
                float v0 = acc[f][nf][half_i * 2 + 0];
                float v1 = acc[f][nf][half_i * 2 + 1];
                if (BIAS) { v0 += bias[col]; v1 += bias[col + 1]; }
                if (RES) {
                    const float* rp = res + (size_t)row * N + col;
                    v0 += rp[0]; v1 += rp[1];
                }
                if (RELU) { v0 = fmaxf(v0, 0.f); v1 = fmaxf(v1, 0.f); }
                if (sizeof(OutT) == 2) {
                    __half2 hv = __floats2half2_rn(v0, v1);
                    *(__half2*)((__half*)C + (size_t)row * N + col) = hv;
                } else {
                    float2 w; w.x = v0; w.y = v1;
                    *(float2*)((float*)C + (size_t)row * N + col) = w;
                }
            }
        }
    }
}

// =====================================================================
// fp16 flash attention (R10 structure), explicit 2-CTA residency.
// =====================================================================
#define KSW_BYTES 8192
#define P2_STRIDE 36
#define P2_BYTES  (128 * P2_STRIDE * 4)
#define ATTF_SMEM (4 * KSW_BYTES + P2_BYTES)  // 51200

__global__ void __launch_bounds__(256, 2) attn_fp16_kernel(
    const __half* __restrict__ qkv, __half* __restrict__ out)
{
    extern __shared__ char sm[];
    unsigned sbase = (unsigned)__cvta_generic_to_shared(sm);
    unsigned* p2sm = (unsigned*)(sm + 4 * KSW_BYTES);
    unsigned p2base = sbase + 4 * KSW_BYTES;

    int tid = threadIdx.x;
    int warp = tid >> 5;
    int lane = tid & 31;
    int gg = lane >> 2;
    int cc = lane & 3;
    int wm = warp * 16;

    int bh = blockIdx.y;
    int b = bh >> 4;
    int h = bh & 15;
    size_t tokbase = (size_t)b * SEQ + blockIdx.x * 128;
    const __half* qb = qkv + tokbase * (3 * DIM) + h * DH;

    auto load_kv = [&](int kt, int s) {
        const __half* kp = qkv + ((size_t)b * SEQ + kt) * (3 * DIM) + DIM + h * DH;
        const __half* vp = kp + DIM;
        unsigned kdst = sbase + s * KSW_BYTES;
        unsigned vdst = sbase + (2 + s) * KSW_BYTES;
#pragma unroll
        for (int j = 0; j < 2; j++) {
            int idx = tid + j * 256;
            int r = idx >> 3, c = idx & 7;
            unsigned off = (unsigned)(r * 128 + c * 16);
            unsigned sw = off ^ ((unsigned)(r & 7) << 4);
            cp16(kdst + sw, kp + (size_t)r * (3 * DIM) + c * 8);
            cp16(vdst + sw, vp + (size_t)r * (3 * DIM) + c * 8);
        }
        cp_commit();
    };

    load_kv(0, 0);

    unsigned qf[4][4];
    {
        const float SC = ATT_SCALE * LOG2E;
        const __half* r0 = qb + (size_t)(wm + gg) * (3 * DIM);
        const __half* r1 = qb + (size_t)(wm + gg + 8) * (3 * DIM);
#pragma unroll
        for (int kf = 0; kf < 4; kf++) {
            int c0 = kf * 16 + 2 * cc;
#pragma unroll
            for (int q = 0; q < 4; q++) {
                const __half* rp = (q & 1) ? r1 : r0;
                int cofs = c0 + ((q >> 1) ? 8 : 0);
                float2 f = __half22float2(*(const __half2*)(rp + cofs));
                __half2 v = __floats2half2_rn(f.x * SC, f.y * SC);
                qf[kf][q] = *(unsigned*)&v;
            }
        }
    }

    float of[8][4];
#pragma unroll
    for (int nf = 0; nf < 8; nf++)
#pragma unroll
        for (int q = 0; q < 4; q++) of[nf][q] = 0.f;
    float m0 = -1e30f, m1 = -1e30f, l0 = 0.f, l1 = 0.f;

    int l15 = lane & 15;

    for (int t = 0; t < SEQ / 64; t++) {
        cp_wait0();
        __syncthreads();
        if (t + 1 < SEQ / 64) load_kv((t + 1) * 64, (t + 1) & 1);

        unsigned kb_s = sbase + (t & 1) * KSW_BYTES;
        unsigned vb_s = sbase + (2 + (t & 1)) * KSW_BYTES;

        float s[8][4];
#pragma unroll
        for (int nf = 0; nf < 8; nf++)
#pragma unroll
            for (int q = 0; q < 4; q++) s[nf][q] = 0.f;

#pragma unroll
        for (int kf = 0; kf < 4; kf++) {
#pragma unroll
            for (int nfp = 0; nfp < 4; nfp++) {
                unsigned row = (unsigned)(nfp * 16 + (lane & 7) + ((lane & 16) ? 8 : 0));
                unsigned off = row * 128 + (unsigned)(kf * 32 + ((lane & 8) ? 16 : 0));
                unsigned addr = kb_s + (off ^ ((row & 7) << 4));
                unsigned b0, b1, b2, b3;
                ldsm_x4(b0, b1, b2, b3, addr);
                mma_fp16(s[2 * nfp], qf[kf], b0, b1);
                mma_fp16(s[2 * nfp + 1], qf[kf], b2, b3);
            }
        }

        float rmax0 = -1e30f, rmax1 = -1e30f;
#pragma unroll
        for (int nf = 0; nf < 8; nf++) {
            rmax0 = fmaxf(rmax0, fmaxf(s[nf][0], s[nf][1]));
            rmax1 = fmaxf(rmax1, fmaxf(s[nf][2], s[nf][3]));
        }
        rmax0 = fmaxf(rmax0, __shfl_xor_sync(0xffffffffu, rmax0, 1));
        rmax0 = fmaxf(rmax0, __shfl_xor_sync(0xffffffffu, rmax0, 2));
        rmax1 = fmaxf(rmax1, __shfl_xor_sync(0xffffffffu, rmax1, 1));
        rmax1 = fmaxf(rmax1, __shfl_xor_sync(0xffffffffu, rmax1, 2));

        float mn0 = fmaxf(m0, rmax0);
        float mn1 = fmaxf(m1, rmax1);
        float f0 = exp2f(m0 - mn0);
        float f1 = exp2f(m1 - mn1);
        m0 = mn0; m1 = mn1;

        float rs0 = 0.f, rs1 = 0.f;
#pragma unroll
        for (int nf = 0; nf < 8; nf++) {
            __half2 hd0 = __floats2half2_rn(s[nf][0] - mn0, s[nf][1] - mn0);
            __half2 hd1 = __floats2half2_rn(s[nf][2] - mn1, s[nf][3] - mn1);
            unsigned hp0 = ex2_f16x2(*(unsigned*)&hd0);
            unsigned hp1 = ex2_f16x2(*(unsigned*)&hd1);
            float2 pf0 = __half22float2(*(__half2*)&hp0);
            float2 pf1 = __half22float2(*(__half2*)&hp1);
            rs0 += pf0.x + pf0.y;
            rs1 += pf1.x + pf1.y;
            p2sm[(wm + gg) * P2_STRIDE + nf * 4 + cc] = hp0;
            p2sm[(wm + gg + 8) * P2_STRIDE + nf * 4 + cc] = hp1;
        }
        rs0 += __shfl_xor_sync(0xffffffffu, rs0, 1);
        rs0 += __shfl_xor_sync(0xffffffffu, rs0, 2);
        rs1 += __shfl_xor_sync(0xffffffffu, rs1, 1);
        rs1 += __shfl_xor_sync(0xffffffffu, rs1, 2);
        l0 = l0 * f0 + rs0;
        l1 = l1 * f1 + rs1;

#pragma unroll
        for (int nf = 0; nf < 8; nf++) {
            of[nf][0] *= f0; of[nf][1] *= f0;
            of[nf][2] *= f1; of[nf][3] *= f1;
        }
        __syncwarp();

#pragma unroll
        for (int kf = 0; kf < 4; kf++) {
            unsigned a[4];
            unsigned pa = p2base + (unsigned)(wm + l15) * (P2_STRIDE * 4)
                        + (unsigned)(kf * 32 + ((lane & 16) ? 16 : 0));
            ldsm_x4(a[0], a[1], a[2], a[3], pa);
#pragma unroll
            for (int nfp = 0; nfp < 4; nfp++) {
                unsigned row = (unsigned)(kf * 16 + l15);
                unsigned off = row * 128 + (unsigned)(nfp * 32 + ((lane & 16) ? 16 : 0));
                unsigned addr = vb_s + (off ^ ((row & 7) << 4));
                unsigned b0, b1, b2, b3;
                ldsm_x4_t(b0, b1, b2, b3, addr);
                mma_fp16(of[2 * nfp], a, b0, b1);
                mma_fp16(of[2 * nfp + 1], a, b2, b3);
            }
        }
    }

    float inv0 = 1.0f / l0;
    float inv1 = 1.0f / l1;
    __half* op = out + tokbase * DIM + h * DH;
#pragma unroll
    for (int nf = 0; nf < 8; nf++) {
        int c0 = nf * 8 + 2 * cc;
        __half2 w0 = __floats2half2_rn(of[nf][0] * inv0, of[nf][1] * inv0);
        __half2 w1 = __floats2half2_rn(of[nf][2] * inv1, of[nf][3] * inv1);
        *(__half2*)(op + (size_t)(wm + gg) * DIM + c0)     = w0;
        *(__half2*)(op + (size_t)(wm + gg + 8) * DIM + c0) = w1;
    }
}

// =====================================================================
// launch — packs on side stream (overlapped), R13 GEMM config.
// =====================================================================
extern "C" void kernel_launch(void* const* d_in, const int* in_sizes, int n_in,
                              void* d_out, int out_size)
{
    const float* x      = (const float*)d_in[0];
    const float* w_qkv  = (const float*)d_in[1];
    const float* w_out  = (const float*)d_in[2];
    const float* b_out  = (const float*)d_in[3];
    const float* w1     = (const float*)d_in[4];
    const float* b1     = (const float*)d_in[5];
    const float* w2     = (const float*)d_in[6];
    const float* b2     = (const float*)d_in[7];
    const float* gamma1 = (const float*)d_in[8];
    const float* beta1  = (const float*)d_in[9];
    const float* gamma2 = (const float*)d_in[10];
    const float* beta2  = (const float*)d_in[11];
    float* out = (float*)d_out;

    __half *xn, *qkv, *att, *h, *ff;
    float *x1;
    unsigned *wqkv, *wout, *w1p, *w2p;
    cudaGetSymbolAddress((void**)&xn,   g_xn);
    cudaGetSymbolAddress((void**)&qkv,  g_qkv);
    cudaGetSymbolAddress((void**)&att,  g_att);
    cudaGetSymbolAddress((void**)&x1,   g_x1);
    cudaGetSymbolAddress((void**)&h,    g_h);
    cudaGetSymbolAddress((void**)&ff,   g_ff);
    cudaGetSymbolAddress((void**)&wqkv, g_wqkv);
    cudaGetSymbolAddress((void**)&wout, g_wout);
    cudaGetSymbolAddress((void**)&w1p,  g_w1);
    cudaGetSymbolAddress((void**)&w2p,  g_w2);

    static bool init_done = false;
    static cudaStream_t sB;
    static cudaEvent_t evFork, evQkv, evRest;
    if (!init_done) {
        cudaFuncSetAttribute(gemm_fp16_kernel<__half, false, false, false>,
                             cudaFuncAttributeMaxDynamicSharedMemorySize, GEMM_SMEM_BYTES);
        cudaFuncSetAttribute(gemm_fp16_kernel<float, true, false, true>,
                             cudaFuncAttributeMaxDynamicSharedMemorySize, GEMM_SMEM_BYTES);
        cudaFuncSetAttribute(gemm_fp16_kernel<__half, true, true, false>,
                             cudaFuncAttributeMaxDynamicSharedMemorySize, GEMM_SMEM_BYTES);
        cudaFuncSetAttribute(attn_fp16_kernel,
                             cudaFuncAttributeMaxDynamicSharedMemorySize, ATTF_SMEM);
        cudaStreamCreateWithFlags(&sB, cudaStreamNonBlocking);
        cudaEventCreateWithFlags(&evFork, cudaEventDisableTiming);
        cudaEventCreateWithFlags(&evQkv,  cudaEventDisableTiming);
        cudaEventCreateWithFlags(&evRest, cudaEventDisableTiming);
        init_done = true;
    }

    // ---- fork side stream ----
    cudaEventRecord(evFork, 0);
    cudaStreamWaitEvent(sB, evFork, 0);

    packT_w_kernel<<<dim3(3 * DIM / 32, DIM / 64), 256, 0, sB>>>(w_qkv, wqkv, DIM, 3 * DIM);
    cudaEventRecord(evQkv, sB);
    packT_w_kernel<<<dim3(DIM / 32, DIM / 64), 256, 0, sB>>>(w_out, wout, DIM, DIM);
    packT_w_kernel<<<dim3(HID / 32, DIM / 64), 256, 0, sB>>>(w1, w1p, DIM, HID);
    packT_w_kernel<<<dim3(DIM / 32, HID / 64), 256, 0, sB>>>(w2, w2p, HID, DIM);
    cudaEventRecord(evRest, sB);

    // 1) xn = fp16(LN1(x))
    ln_kernel<<<TOK / 8, 256>>>(x, gamma1, beta1, xn);

    cudaStreamWaitEvent(0, evQkv, 0);

    // 2) qkv = fp16(xn @ w_qkv)
    gemm_fp16_kernel<__half, false, false, false>
        <<<dim3(3 * DIM / 128, TOK / 128), 128, GEMM_SMEM_BYTES>>>(
        xn, wqkv, nullptr, nullptr, qkv, TOK, 3 * DIM, DIM);

    // 3) att = fp16(attention(qkv))
    attn_fp16_kernel<<<dim3(SEQ / 128, BATCH * HEADS), 256, ATTF_SMEM>>>(qkv, att);

    cudaStreamWaitEvent(0, evRest, 0);

    // 4) x1 = x + att @ w_out + b_out    (fp32)
    gemm_fp16_kernel<float, true, false, true>
        <<<dim3(DIM / 128, TOK / 128), 128, GEMM_SMEM_BYTES>>>(
        att, wout, b_out, x, x1, TOK, DIM, DIM);

    // 5) h = fp16(LN2(x1))
    ln_kernel<<<TOK / 8, 256>>>(x1, gamma2, beta2, h);

    // 6) ff = fp16(relu(h @ w1 + b1))
    gemm_fp16_kernel<__half, true, true, false>
        <<<dim3(HID / 128, TOK / 128), 128, GEMM_SMEM_BYTES>>>(
        h, w1p, b1, nullptr, ff, TOK, HID, DIM);

    // 7) out = x1 + ff @ w2 + b2   (fp32)
    gemm_fp16_kernel<float, true, false, true>
        <<<dim3(DIM / 128, TOK / 128), 128, GEMM_SMEM_BYTES>>>(
        ff, w2p, b2, x1, out, TOK, DIM, HID);
}